// round 3
// baseline (speedup 1.0000x reference)
#include <cuda_runtime.h>
#include <cuda_bf16.h>
#include <cstdint>

#define VOCABN 50257
#define EMBN   256
#define HIDN   256
#define BN     64
#define TN     2048

// Precomputed input-gate table: G[v][col] = emb[v] @ W_ih^T + b_ih, bf16.
// 50257*768*2B = 77.2 MB static device scratch (allowed; no cudaMalloc).
__device__ __nv_bfloat16 g_G[(size_t)VOCABN * 768];

// ============================================================================
// Kernel 1: build G table.  Grid = ceil(50257/64) CTAs, 256 threads.
// Each CTA: 64 vocab rows x 768 cols, 6 passes of 128 cols.
// smem: embS[64][257] + WS[128][257] fp32 (padded, conflict-free).
// ============================================================================
#define P_SMEM ((64*257 + 128*257) * 4)

__global__ void __launch_bounds__(256) prep_g(const float* __restrict__ emb,
                                              const float* __restrict__ W_ih,
                                              const float* __restrict__ b_ih)
{
    extern __shared__ float sm1[];
    float* embS = sm1;              // [64][257]
    float* WS   = sm1 + 64 * 257;   // [128][257]
    const int tid = threadIdx.x;
    const int v0  = blockIdx.x * 64;

    // load emb tile (coalesced)
    for (int idx = tid; idx < 64 * 256; idx += 256) {
        int v = idx >> 8, k = idx & 255;
        int gv = v0 + v;
        embS[v * 257 + k] = (gv < VOCABN) ? emb[(size_t)gv * EMBN + k] : 0.0f;
    }

    const int tx = tid & 31;   // j-lane (strided j assignment -> conflict-free W LDS)
    const int ty = tid >> 5;   // v-group (broadcast emb LDS)

    for (int jt = 0; jt < 6; jt++) {
        __syncthreads();
        for (int idx = tid; idx < 128 * 256; idx += 256) {
            int r = idx >> 8, k = idx & 255;
            WS[r * 257 + k] = W_ih[(size_t)(jt * 128 + r) * EMBN + k];
        }
        __syncthreads();

        float acc[8][4];
        #pragma unroll
        for (int a = 0; a < 8; a++)
            #pragma unroll
            for (int c = 0; c < 4; c++) acc[a][c] = 0.0f;

        #pragma unroll 4
        for (int k = 0; k < 256; k++) {
            float w[4];
            #pragma unroll
            for (int jj = 0; jj < 4; jj++) w[jj] = WS[(tx + jj * 32) * 257 + k];
            #pragma unroll
            for (int vv = 0; vv < 8; vv++) {
                float e = embS[(ty * 8 + vv) * 257 + k];
                #pragma unroll
                for (int jj = 0; jj < 4; jj++) acc[vv][jj] += e * w[jj];
            }
        }

        #pragma unroll
        for (int jj = 0; jj < 4; jj++) {
            int col = jt * 128 + tx + jj * 32;
            float bi = b_ih[col];
            #pragma unroll
            for (int vv = 0; vv < 8; vv++) {
                int v = v0 + ty * 8 + vv;
                if (v < VOCABN)
                    g_G[(size_t)v * 768 + col] = __float2bfloat16(acc[vv][jj] + bi);
            }
        }
    }
}

// ============================================================================
// Kernel 2: GRU recurrence. Cluster (2,1,1); grid 128 CTAs = 64 clusters
// (1 batch element per cluster). CTA rank r owns hidden slots
// jg in [r*128, r*128+128) -> W_hh rows {jg, 256+jg, 512+jg} = 384 rows
// stored bf16-packed transposed in smem: WT[kpair][row], 196.6 KB.
// h (fp32, full 256) double-buffered in smem; halves exchanged via DSMEM
// (mapa + st.shared::cluster) + one barrier.cluster per step.
// gi rows gathered from g_G with a cp.async ring, 6 steps lookahead.
// ============================================================================
#define LOOK 6
// smem byte offsets
#define OFF_WT   0         // 128*384*4 = 196608
#define OFF_TOK  196608    // 2048*4    = 8192
#define OFF_H    204800    // 2*256*4   = 2048
#define OFF_GH   206848    // 384*4     = 1536
#define OFF_RING 208384    // 8*384*2   = 6144
#define R_SMEM   214528

__device__ __forceinline__ float sigmoidf_(float x) { return 1.0f / (1.0f + __expf(-x)); }
__device__ __forceinline__ float tanhf_(float x)    { float e = __expf(2.0f * x); return 1.0f - 2.0f / (e + 1.0f); }

#define CLUSTER_SYNC_() do { \
    asm volatile("barrier.cluster.arrive.aligned;" ::: "memory"); \
    asm volatile("barrier.cluster.wait.aligned;"   ::: "memory"); \
} while (0)

__global__ void __cluster_dims__(2, 1, 1) __launch_bounds__(384, 1)
gru_rec(const int*   __restrict__ tokens,
        const float* __restrict__ W_hh,
        const float* __restrict__ b_hh,
        const float* __restrict__ W_fc,
        const float* __restrict__ b_fc,
        float*       __restrict__ out)
{
    extern __shared__ char sm2[];
    uint32_t*       WT   = (uint32_t*)(sm2 + OFF_WT);     // [128 kpair][384 row] bf16x2
    int*            toks = (int*)(sm2 + OFF_TOK);         // [2048]
    float*          hbuf = (float*)(sm2 + OFF_H);         // [2][256]
    float*          ghs  = (float*)(sm2 + OFF_GH);        // [384]
    __nv_bfloat16*  ring = (__nv_bfloat16*)(sm2 + OFF_RING); // [8][384]

    const int tid = threadIdx.x;
    unsigned rank; asm("mov.u32 %0, %%cluster_ctarank;" : "=r"(rank));
    const int b = blockIdx.x >> 1;

    // ---- init: tokens, weights->smem(bf16, transposed), h0 = 0 ----
    for (int i = tid; i < TN; i += 384) toks[i] = tokens[b * TN + i];

    for (int idx = tid; idx < 384 * 128; idx += 384) {
        int row  = idx >> 7;      // 0..383 local row
        int kp   = idx & 127;     // k-pair
        int gate = row >> 7;      // 0=r, 1=z, 2=n
        int jl   = row & 127;
        int grow = gate * 256 + (int)rank * 128 + jl;
        float2 w = *(const float2*)(W_hh + (size_t)grow * HIDN + kp * 2);
        __nv_bfloat162 p = __floats2bfloat162_rn(w.x, w.y);
        WT[kp * 384 + row] = *reinterpret_cast<uint32_t*>(&p);
    }
    for (int i = tid; i < 256; i += 384) { hbuf[i] = 0.0f; hbuf[256 + i] = 0.0f; }

    const int   row  = tid;                                        // my gh row
    const int   grow = (row >> 7) * 256 + (int)rank * 128 + (row & 127);
    const float bias = b_hh[grow];

    __syncthreads();
    CLUSTER_SYNC_();

    // gi prefetch: threads 0..47, 16B each (3 chunks of 128 bf16 = 768B/step/CTA)
#define ISSUE_GI(T_) do {                                                          \
    if (tid < 48) {                                                                \
        int tt_ = (T_);                                                            \
        if (tt_ < TN) {                                                            \
            int c_ = tid >> 4, off_ = tid & 15;                                    \
            int tok_ = toks[tt_];                                                  \
            const void* src_ = (const void*)(g_G + (size_t)tok_ * 768              \
                                             + c_ * 256 + (int)rank * 128 + off_ * 8); \
            uint32_t ds_ = (uint32_t)__cvta_generic_to_shared(                     \
                ring + ((tt_ & 7) * 384 + c_ * 128 + off_ * 8));                   \
            asm volatile("cp.async.cg.shared.global [%0], [%1], 16;"               \
                         :: "r"(ds_), "l"(src_) : "memory");                       \
        }                                                                          \
        asm volatile("cp.async.commit_group;" ::: "memory");                       \
    }                                                                              \
} while (0)

    for (int t = 0; t < LOOK; t++) ISSUE_GI(t);

    // ---- recurrence ----
    for (int t = 0; t < TN; t++) {
        ISSUE_GI(t + LOOK);

        const float* h = hbuf + ((t & 1) << 8);
        float acc = bias;
        const uint32_t* wrow = WT + row;
        #pragma unroll 4
        for (int kp = 0; kp < 128; kp += 2) {
            float4 h4 = *(const float4*)(h + kp * 2);     // broadcast LDS.128
            uint32_t w0 = wrow[kp * 384];
            uint32_t w1 = wrow[(kp + 1) * 384];
            acc += __int_as_float(w0 << 16)          * h4.x;
            acc += __int_as_float(w0 & 0xffff0000u)  * h4.y;
            acc += __int_as_float(w1 << 16)          * h4.z;
            acc += __int_as_float(w1 & 0xffff0000u)  * h4.w;
        }
        ghs[row] = acc;

        if (tid < 48) asm volatile("cp.async.wait_group 5;" ::: "memory");
        __syncthreads();

        if (tid < 128) {
            const __nv_bfloat16* gi = ring + ((t & 7) * 384);
            float rg = sigmoidf_(__bfloat162float(gi[tid])       + ghs[tid]);
            float zg = sigmoidf_(__bfloat162float(gi[128 + tid]) + ghs[128 + tid]);
            float ng = tanhf_(__bfloat162float(gi[256 + tid]) + rg * ghs[256 + tid]);
            int jg = (int)rank * 128 + tid;
            float hn = (1.0f - zg) * ng + zg * h[jg];
            float* dstl = hbuf + (((t + 1) & 1) << 8) + jg;
            *dstl = hn;                                    // local copy
            uint32_t la = (uint32_t)__cvta_generic_to_shared(dstl);
            uint32_t ra;
            asm("mapa.shared::cluster.u32 %0, %1, %2;" : "=r"(ra) : "r"(la), "r"(rank ^ 1u));
            asm volatile("st.shared::cluster.f32 [%0], %1;" :: "r"(ra), "f"(hn) : "memory");
        }
        // release my h-half writes to peer; acquire peer's half. One sync/step
        // is sufficient with the double-buffered h.
        CLUSTER_SYNC_();
    }

    // ---- final FC + sigmoid (rank 0, warp 0). TN even -> h_T in hbuf[0] ----
    if (rank == 0 && tid < 32) {
        const float* h = hbuf;
        float a0 = 0.0f, a1 = 0.0f;
        #pragma unroll
        for (int j = tid; j < 256; j += 32) {
            float hv = h[j];
            a0 += hv * W_fc[j];
            a1 += hv * W_fc[256 + j];
        }
        #pragma unroll
        for (int s = 16; s > 0; s >>= 1) {
            a0 += __shfl_xor_sync(0xffffffffu, a0, s);
            a1 += __shfl_xor_sync(0xffffffffu, a1, s);
        }
        if (tid == 0) {
            out[b * 2 + 0] = sigmoidf_(a0 + b_fc[0]);
            out[b * 2 + 1] = sigmoidf_(a1 + b_fc[1]);
        }
    }
}

// ============================================================================
// launch
// ============================================================================
extern "C" void kernel_launch(void* const* d_in, const int* in_sizes, int n_in,
                              void* d_out, int out_size)
{
    const int*   tokens = (const int*)d_in[0];
    const float* emb    = (const float*)d_in[1];
    const float* W_ih   = (const float*)d_in[2];
    const float* W_hh   = (const float*)d_in[3];
    const float* b_ih   = (const float*)d_in[4];
    const float* b_hh   = (const float*)d_in[5];
    const float* W_fc   = (const float*)d_in[6];
    const float* b_fc   = (const float*)d_in[7];
    float* out = (float*)d_out;
    (void)in_sizes; (void)n_in; (void)out_size;

    cudaFuncSetAttribute(prep_g,  cudaFuncAttributeMaxDynamicSharedMemorySize, P_SMEM);
    cudaFuncSetAttribute(gru_rec, cudaFuncAttributeMaxDynamicSharedMemorySize, R_SMEM);

    prep_g<<<(VOCABN + 63) / 64, 256, P_SMEM>>>(emb, W_ih, b_ih);
    gru_rec<<<128, 384, R_SMEM>>>(tokens, W_hh, b_hh, W_fc, b_fc, out);
}

// round 5
// speedup vs baseline: 1.0202x; 1.0202x over previous
#include <cuda_runtime.h>
#include <cuda_bf16.h>
#include <cstdint>

#define VOCABN 50257
#define EMBN   256
#define HIDN   256
#define TN     2048

// Precomputed input-gate table: G[v][col] = emb[v] @ W_ih^T + b_ih, bf16. 77MB.
__device__ __nv_bfloat16 g_G[(size_t)VOCABN * 768];

// ---------------- packed f32x2 helpers (base sm_100 ISA) ----------------
__device__ __forceinline__ void fma2(unsigned long long& acc,
                                     unsigned long long a, unsigned long long b) {
    asm("fma.rn.f32x2 %0, %1, %2, %0;" : "+l"(acc) : "l"(a), "l"(b));
}
__device__ __forceinline__ float2 unpk64(unsigned long long v) {
    float2 r; asm("mov.b64 {%0, %1}, %2;" : "=f"(r.x), "=f"(r.y) : "l"(v));
    return r;
}

// ============================================================================
// Kernel 1: build G table. Same structure as R1 (passing), inner loop moved to
// f32x2 packed FMAs (k in pairs), smem row pad 257 -> 258 for 8B alignment.
// ============================================================================
#define PPAD 258
#define P_SMEM ((64*PPAD + 128*PPAD) * 4)

__global__ void __launch_bounds__(256) prep_g(const float* __restrict__ emb,
                                              const float* __restrict__ W_ih,
                                              const float* __restrict__ b_ih)
{
    extern __shared__ float sm1[];
    float* embS = sm1;                 // [64][258]
    float* WS   = sm1 + 64 * PPAD;     // [128][258]
    const int tid = threadIdx.x;
    const int v0  = blockIdx.x * 64;

    for (int idx = tid; idx < 64 * 256; idx += 256) {
        int v = idx >> 8, k = idx & 255;
        int gv = v0 + v;
        embS[v * PPAD + k] = (gv < VOCABN) ? emb[(size_t)gv * EMBN + k] : 0.0f;
    }
    const int tx = tid & 31, ty = tid >> 5;

    for (int jt = 0; jt < 6; jt++) {
        __syncthreads();
        for (int idx = tid; idx < 128 * 256; idx += 256) {
            int r = idx >> 8, k = idx & 255;
            WS[r * PPAD + k] = W_ih[(size_t)(jt * 128 + r) * EMBN + k];
        }
        __syncthreads();

        unsigned long long acc[8][4];
        #pragma unroll
        for (int a = 0; a < 8; a++)
            #pragma unroll
            for (int c = 0; c < 4; c++) acc[a][c] = 0ull;

        #pragma unroll 4
        for (int k = 0; k < 256; k += 2) {
            unsigned long long w2[4], e2[8];
            #pragma unroll
            for (int jj = 0; jj < 4; jj++)
                w2[jj] = *(const unsigned long long*)(WS + (tx + jj * 32) * PPAD + k);
            #pragma unroll
            for (int vv = 0; vv < 8; vv++)
                e2[vv] = *(const unsigned long long*)(embS + (ty * 8 + vv) * PPAD + k);
            #pragma unroll
            for (int vv = 0; vv < 8; vv++)
                #pragma unroll
                for (int jj = 0; jj < 4; jj++)
                    fma2(acc[vv][jj], e2[vv], w2[jj]);
        }

        #pragma unroll
        for (int jj = 0; jj < 4; jj++) {
            int col = jt * 128 + tx + jj * 32;
            float bi = b_ih[col];
            #pragma unroll
            for (int vv = 0; vv < 8; vv++) {
                int v = v0 + ty * 8 + vv;
                if (v < VOCABN) {
                    float2 s = unpk64(acc[vv][jj]);
                    g_G[(size_t)v * 768 + col] = __float2bfloat16(s.x + s.y + bi);
                }
            }
        }
    }
}

// ============================================================================
// Kernel 2: GRU recurrence. Cluster (2,1,1), 64 clusters, 1 batch/cluster.
// Rank r owns rows {g*256 + r*128 + jl}. Weights bf16-packed in smem,
// W64[q][row] = 8B = 4 weights (k=4q..4q+3). Dot uses f32x2 FMAs:
//   lo float = SHL(word,16) exact; hi float = raw word (<=2^-8 mantissa noise).
// k-split: own-half k first (local h), mbar-wait peer, then peer-half k.
// Handshake: st.shared::cluster h + mbarrier.arrive.release.cluster (no
// barrier.cluster / L1 flush in the loop).
// ============================================================================
#define LOOK 6
#define OFF_W    0         // 384*64*8 = 196608
#define OFF_TOK  196608    // 8192
#define OFF_H    204800    // 2*256*4 = 2048
#define OFF_GH   206848    // 384*4
#define OFF_RING 208384    // 8*384*2 = 6144
#define OFF_MBAR 214528    // 8
#define R_SMEM   214656

__device__ __forceinline__ float sigapx(float x) {
    float t; asm("tanh.approx.f32 %0, %1;" : "=f"(t) : "f"(0.5f * x));
    return fmaf(0.5f, t, 0.5f);
}
__device__ __forceinline__ float tanhapx(float x) {
    float t; asm("tanh.approx.f32 %0, %1;" : "=f"(t) : "f"(x)); return t;
}
__device__ __forceinline__ void dot4(unsigned long long& a0, unsigned long long& a1,
                                     uint2 w, float4 h) {
    asm("{\n\t"
        ".reg .b32 t0, t1;\n\t"
        ".reg .b64 wa, wb, hb0, hb1;\n\t"
        "shl.b32 t0, %2, 16;\n\t"
        "shl.b32 t1, %3, 16;\n\t"
        "mov.b64 wa, {t0, %2};\n\t"
        "mov.b64 wb, {t1, %3};\n\t"
        "mov.b64 hb0, {%4, %5};\n\t"
        "mov.b64 hb1, {%6, %7};\n\t"
        "fma.rn.f32x2 %0, wa, hb0, %0;\n\t"
        "fma.rn.f32x2 %1, wb, hb1, %1;\n\t"
        "}" : "+l"(a0), "+l"(a1)
            : "r"(w.x), "r"(w.y), "f"(h.x), "f"(h.y), "f"(h.z), "f"(h.w));
}
__device__ __forceinline__ void mbar_wait(uint32_t mb, uint32_t par) {
    asm volatile("{\n\t.reg .pred P1;\n\t"
        "WL_%=:\n\t"
        "mbarrier.try_wait.parity.acquire.cluster.shared::cta.b64 P1, [%0], %1, 0x989680;\n\t"
        "@P1 bra.uni WD_%=;\n\t"
        "bra.uni WL_%=;\n\t"
        "WD_%=:\n\t}" :: "r"(mb), "r"(par) : "memory");
}

__global__ void __cluster_dims__(2, 1, 1) __launch_bounds__(384, 1)
gru_rec(const int*   __restrict__ tokens,
        const float* __restrict__ W_hh,
        const float* __restrict__ b_hh,
        const float* __restrict__ W_fc,
        const float* __restrict__ b_fc,
        float*       __restrict__ out)
{
    extern __shared__ char sm2[];
    uint2*          W64  = (uint2*)(sm2 + OFF_W);             // [64 q][384 row]
    int*            toks = (int*)(sm2 + OFF_TOK);
    float*          hbuf = (float*)(sm2 + OFF_H);             // [2][256]
    float*          ghs  = (float*)(sm2 + OFF_GH);            // [384]
    __nv_bfloat16*  ring = (__nv_bfloat16*)(sm2 + OFF_RING);  // [8][384]
    const uint32_t  mbar_sa = (uint32_t)__cvta_generic_to_shared(sm2 + OFF_MBAR);

    const int tid = threadIdx.x;
    unsigned rank; asm("mov.u32 %0, %%cluster_ctarank;" : "=r"(rank));
    const int b = blockIdx.x >> 1;

    // ---- init ----
    for (int i = tid; i < TN; i += 384) toks[i] = tokens[b * TN + i];

    {   // my row's weights: pack fp32 -> bf16x2 words, W64[q][tid]
        const int gate = tid >> 7, jl = tid & 127;
        const int grow = gate * 256 + (int)rank * 128 + jl;
        const float4* src = (const float4*)(W_hh + (size_t)grow * HIDN);
        #pragma unroll 4
        for (int q = 0; q < 64; q++) {
            float4 w = src[q];
            __nv_bfloat162 p0 = __floats2bfloat162_rn(w.x, w.y);
            __nv_bfloat162 p1 = __floats2bfloat162_rn(w.z, w.w);
            uint2 e;
            e.x = *reinterpret_cast<uint32_t*>(&p0);
            e.y = *reinterpret_cast<uint32_t*>(&p1);
            W64[q * 384 + tid] = e;
        }
    }
    for (int i = tid; i < 256; i += 384) { hbuf[i] = 0.0f; hbuf[256 + i] = 0.0f; }

    const int   grow = (tid >> 7) * 256 + (int)rank * 128 + (tid & 127);
    const float bias = b_hh[grow];

    if (tid == 0)
        asm volatile("mbarrier.init.shared.b64 [%0], %1;" :: "r"(mbar_sa), "r"(128u) : "memory");
    __syncthreads();
    asm volatile("barrier.cluster.arrive.aligned;" ::: "memory");
    asm volatile("barrier.cluster.wait.aligned;"   ::: "memory");

    // pre-loop arrivals: complete phase 0 on the PEER's mbar (h0 already zero)
    if (tid < 128) {
        uint32_t rb;
        asm("mapa.shared::cluster.u32 %0, %1, %2;" : "=r"(rb) : "r"(mbar_sa), "r"(rank ^ 1u));
        asm volatile("mbarrier.arrive.release.cluster.shared::cluster.b64 _, [%0];"
                     :: "r"(rb) : "memory");
    }

#define ISSUE_GI(T_) do {                                                          \
    if (tid < 48) {                                                                \
        int tt_ = (T_);                                                            \
        if (tt_ < TN) {                                                            \
            int c_ = tid >> 4, off_ = tid & 15;                                    \
            int tok_ = toks[tt_];                                                  \
            const void* src_ = (const void*)(g_G + (size_t)tok_ * 768              \
                                             + c_ * 256 + (int)rank * 128 + off_ * 8); \
            uint32_t ds_ = (uint32_t)__cvta_generic_to_shared(                     \
                ring + ((tt_ & 7) * 384 + c_ * 128 + off_ * 8));                   \
            asm volatile("cp.async.cg.shared.global [%0], [%1], 16;"               \
                         :: "r"(ds_), "l"(src_) : "memory");                       \
        }                                                                          \
        asm volatile("cp.async.commit_group;" ::: "memory");                       \
    }                                                                              \
} while (0)

    for (int t = 0; t < LOOK; t++) ISSUE_GI(t);

    const uint2* Wp = W64 + tid;
    const int q_own = (int)rank * 32;        // own-half k = [rank*128, rank*128+128)
    const int q_oth = 32 - q_own;            // rank0 -> 32, rank1 -> 0

#define DOT_HALF(Q0)                                        \
    _Pragma("unroll 8")                                     \
    for (int q = (Q0); q < (Q0) + 32; q++) {                \
        uint2  wv = Wp[q * 384];                            \
        float4 h4 = *(const float4*)(h + q * 4);            \
        dot4(acc0, acc1, wv, h4);                           \
    }

    // ---- recurrence ----
    for (int t = 0; t < TN; t++) {
        const float* h = hbuf + ((t & 1) << 8);
        unsigned long long acc0 = 0ull, acc1 = 0ull;

        DOT_HALF(q_own);                  // local h-half (ready after last bar)
        mbar_wait(mbar_sa, (uint32_t)(t & 1));   // peer h-half arrivals
        DOT_HALF(q_oth);

        unsigned long long s;
        asm("add.rn.f32x2 %0, %1, %2;" : "=l"(s) : "l"(acc0), "l"(acc1));
        float2 p = unpk64(s);
        ghs[tid] = p.x + p.y + bias;

        ISSUE_GI(t + LOOK);
        if (tid < 48) asm volatile("cp.async.wait_group 5;" ::: "memory");
        __syncthreads();

        if (tid < 128) {
            const __nv_bfloat16* gi = ring + ((t & 7) * 384);
            float rg = sigapx(__bfloat162float(gi[tid])       + ghs[tid]);
            float zg = sigapx(__bfloat162float(gi[128 + tid]) + ghs[128 + tid]);
            float ng = tanhapx(__bfloat162float(gi[256 + tid]) + rg * ghs[256 + tid]);
            int jg = (int)rank * 128 + tid;
            float hn = ng + zg * (h[jg] - ng);
            float* dstl = hbuf + (((t + 1) & 1) << 8) + jg;
            *dstl = hn;                                       // local
            uint32_t la = (uint32_t)__cvta_generic_to_shared(dstl);
            uint32_t ra, rb;
            asm("mapa.shared::cluster.u32 %0, %1, %2;" : "=r"(ra) : "r"(la), "r"(rank ^ 1u));
            asm volatile("st.shared::cluster.f32 [%0], %1;" :: "r"(ra), "f"(hn) : "memory");
            asm("mapa.shared::cluster.u32 %0, %1, %2;" : "=r"(rb) : "r"(mbar_sa), "r"(rank ^ 1u));
            asm volatile("mbarrier.arrive.release.cluster.shared::cluster.b64 _, [%0];"
                         :: "r"(rb) : "memory");
        }
        __syncthreads();   // local h visible; ghs safe to overwrite next step
    }

    // final peer writes visible + no early exit while peer may write our smem
    asm volatile("barrier.cluster.arrive.aligned;" ::: "memory");
    asm volatile("barrier.cluster.wait.aligned;"   ::: "memory");

    // ---- final FC + sigmoid (rank 0, warp 0). h_T in hbuf[0] ----
    if (rank == 0 && tid < 32) {
        float a0 = 0.0f, a1 = 0.0f;
        #pragma unroll
        for (int j = tid; j < 256; j += 32) {
            float hv = hbuf[j];
            a0 += hv * W_fc[j];
            a1 += hv * W_fc[256 + j];
        }
        #pragma unroll
        for (int s = 16; s > 0; s >>= 1) {
            a0 += __shfl_xor_sync(0xffffffffu, a0, s);
            a1 += __shfl_xor_sync(0xffffffffu, a1, s);
        }
        if (tid == 0) {
            out[b * 2 + 0] = 1.0f / (1.0f + __expf(-(a0 + b_fc[0])));
            out[b * 2 + 1] = 1.0f / (1.0f + __expf(-(a1 + b_fc[1])));
        }
    }
}

// ============================================================================
extern "C" void kernel_launch(void* const* d_in, const int* in_sizes, int n_in,
                              void* d_out, int out_size)
{
    const int*   tokens = (const int*)d_in[0];
    const float* emb    = (const float*)d_in[1];
    const float* W_ih   = (const float*)d_in[2];
    const float* W_hh   = (const float*)d_in[3];
    const float* b_ih   = (const float*)d_in[4];
    const float* b_hh   = (const float*)d_in[5];
    const float* W_fc   = (const float*)d_in[6];
    const float* b_fc   = (const float*)d_in[7];
    float* out = (float*)d_out;
    (void)in_sizes; (void)n_in; (void)out_size;

    cudaFuncSetAttribute(prep_g,  cudaFuncAttributeMaxDynamicSharedMemorySize, P_SMEM);
    cudaFuncSetAttribute(gru_rec, cudaFuncAttributeMaxDynamicSharedMemorySize, R_SMEM);

    prep_g<<<(VOCABN + 63) / 64, 256, P_SMEM>>>(emb, W_ih, b_ih);
    gru_rec<<<128, 384, R_SMEM>>>(tokens, W_hh, b_hh, W_fc, b_fc, out);
}